// round 1
// baseline (speedup 1.0000x reference)
#include <cuda_runtime.h>
#include <stddef.h>

// Problem constants
#define BB 4
#define SS 2048
#define DD 1024
#define HH 16
#define DEPTH 64
#define QBLK 8

// Scratch (allocation-free: __device__ globals)
__device__ float g_q[(size_t)BB * SS * DD];
__device__ float g_k[(size_t)BB * SS * DD];
__device__ float g_v[(size_t)BB * SS * DD];
__device__ float g_c[(size_t)BB * SS * DD];

// ---------------------------------------------------------------------------
// GEMM: C[M,N] = A[M,K] @ W[K,N] + bias[N]   (all fp32, row-major)
// 64x64 block tile, K-slice 16, 4x4 microtile per thread, 256 threads.
// ---------------------------------------------------------------------------
__global__ __launch_bounds__(256) void gemm_bias_kernel(
    const float* __restrict__ A, const float* __restrict__ W,
    const float* __restrict__ bias, float* __restrict__ C,
    int M, int N, int K)
{
    __shared__ float As[16][68];   // [k][m], padded
    __shared__ float Bs[16][68];   // [k][n], padded

    const int tid = threadIdx.x;
    const int tx = tid & 15;       // n direction (4 cols each)
    const int ty = tid >> 4;       // m direction (4 rows each)
    const int bm = blockIdx.y * 64;
    const int bn = blockIdx.x * 64;

    // A-tile load mapping: 64 rows x 16 k = 256 float4 (one per thread)
    const int am = tid >> 2;            // 0..63
    const int ak = (tid & 3) << 2;      // 0,4,8,12
    // B-tile load mapping: 16 k x 64 n = 256 float4
    const int bk = tid >> 4;            // 0..15
    const int bn4 = (tid & 15) << 2;    // 0..60

    const float* Aptr = A + (size_t)(bm + am) * K + ak;
    const float* Wptr = W + (size_t)bk * N + bn + bn4;

    float acc[4][4];
#pragma unroll
    for (int r = 0; r < 4; r++)
#pragma unroll
        for (int c = 0; c < 4; c++) acc[r][c] = 0.f;

    for (int k0 = 0; k0 < K; k0 += 16) {
        float4 av = *(const float4*)(Aptr + k0);
        float4 bv = *(const float4*)(Wptr + (size_t)k0 * N);
        __syncthreads();
        As[ak + 0][am] = av.x;
        As[ak + 1][am] = av.y;
        As[ak + 2][am] = av.z;
        As[ak + 3][am] = av.w;
        *(float4*)&Bs[bk][bn4] = bv;
        __syncthreads();

#pragma unroll
        for (int k = 0; k < 16; k++) {
            float4 a = *(const float4*)&As[k][ty << 2];
            float4 b = *(const float4*)&Bs[k][tx << 2];
            acc[0][0] += a.x * b.x; acc[0][1] += a.x * b.y; acc[0][2] += a.x * b.z; acc[0][3] += a.x * b.w;
            acc[1][0] += a.y * b.x; acc[1][1] += a.y * b.y; acc[1][2] += a.y * b.z; acc[1][3] += a.y * b.w;
            acc[2][0] += a.z * b.x; acc[2][1] += a.z * b.y; acc[2][2] += a.z * b.z; acc[2][3] += a.z * b.w;
            acc[3][0] += a.w * b.x; acc[3][1] += a.w * b.y; acc[3][2] += a.w * b.z; acc[3][3] += a.w * b.w;
        }
    }

    float4 bb = *(const float4*)&bias[bn + (tx << 2)];
#pragma unroll
    for (int r = 0; r < 4; r++) {
        float4 o;
        o.x = acc[r][0] + bb.x;
        o.y = acc[r][1] + bb.y;
        o.z = acc[r][2] + bb.z;
        o.w = acc[r][3] + bb.w;
        *(float4*)&C[(size_t)(bm + (ty << 2) + r) * N + bn + (tx << 2)] = o;
    }
}

// ---------------------------------------------------------------------------
// Attention: per block -> 8 query rows of one (b,h).
//  Phase A: scores (8 x 2048) into smem, K chunks staged transposed in smem.
//  Phase B: warp-per-row softmax; write attn probs to global (if requested).
//  Phase C: rep = P @ V, V chunks staged in smem; write into concat buffer.
// Dynamic smem: sc 8*2048 | kt 64*65 (aliased as vt 64*64) | qt 8*64
// ---------------------------------------------------------------------------
#define ATT_SMEM_FLOATS (8 * 2048 + 64 * 65 + 8 * 64)
#define ATT_SMEM_BYTES  (ATT_SMEM_FLOATS * 4)

__global__ __launch_bounds__(256) void attn_kernel(
    const float* __restrict__ Qp, const float* __restrict__ Kp,
    const float* __restrict__ Vp, const float* __restrict__ Mask,
    float* __restrict__ attn_out, float* __restrict__ concat)
{
    extern __shared__ float sm[];
    float* sc = sm;                    // [8][2048]
    float* kt = sm + 8 * 2048;         // [64][65] (k-transposed) / [64][64] vt
    float* qt = kt + 64 * 65;          // [8][64]

    const int tid = threadIdx.x;
    const int qbase = blockIdx.x * QBLK;
    const int h = blockIdx.y;
    const int b = blockIdx.z;

    // load q tile
    for (int i = tid; i < QBLK * DEPTH; i += 256) {
        int r = i >> 6, d = i & 63;
        qt[i] = Qp[((size_t)b * SS + qbase + r) * DD + h * DEPTH + d];
    }

    const int j  = tid & 63;   // key idx (phase A) / depth idx (phase C)
    const int rg = tid >> 6;   // row group 0..3 -> rows rg, rg+4

    const size_t mrow0 = ((size_t)b * SS + qbase + rg) * SS;
    const size_t mrow1 = ((size_t)b * SS + qbase + rg + 4) * SS;

    // ---- Phase A: scores ----
    for (int kc = 0; kc < SS / 64; kc++) {
        __syncthreads();
        const float* kchunk = Kp + ((size_t)b * SS + kc * 64) * DD + h * DEPTH;
        for (int i = tid; i < 1024; i += 256) {       // 64 keys * 16 float4
            int key = i >> 4, d4 = (i & 15) << 2;
            float4 v = *(const float4*)(kchunk + (size_t)key * DD + d4);
            kt[(d4 + 0) * 65 + key] = v.x;
            kt[(d4 + 1) * 65 + key] = v.y;
            kt[(d4 + 2) * 65 + key] = v.z;
            kt[(d4 + 3) * 65 + key] = v.w;
        }
        __syncthreads();

        float s0 = 0.f, s1 = 0.f;
#pragma unroll
        for (int d = 0; d < DEPTH; d++) {
            float kv = kt[d * 65 + j];
            s0 += qt[rg * 64 + d] * kv;
            s1 += qt[(rg + 4) * 64 + d] * kv;
        }
        int key = kc * 64 + j;
        sc[rg * SS + key]       = s0 * 0.125f + Mask[mrow0 + key] * (-1e9f);
        sc[(rg + 4) * SS + key] = s1 * 0.125f + Mask[mrow1 + key] * (-1e9f);
    }
    __syncthreads();

    // ---- Phase B: softmax (warp w owns row w) ----
    {
        const int w = tid >> 5, lane = tid & 31;
        float* row = sc + (size_t)w * SS;
        float m = -3.4e38f;
        for (int i = lane; i < SS; i += 32) m = fmaxf(m, row[i]);
#pragma unroll
        for (int o = 16; o > 0; o >>= 1) m = fmaxf(m, __shfl_xor_sync(0xffffffffu, m, o));
        float sum = 0.f;
        for (int i = lane; i < SS; i += 32) {
            float e = __expf(row[i] - m);
            row[i] = e;
            sum += e;
        }
#pragma unroll
        for (int o = 16; o > 0; o >>= 1) sum += __shfl_xor_sync(0xffffffffu, sum, o);
        float inv = 1.0f / sum;
        if (attn_out) {
            float* arow = attn_out + (((size_t)b * HH + h) * SS + qbase + w) * SS;
            for (int i = lane; i < SS; i += 32) {
                float p = row[i] * inv;
                row[i] = p;
                arow[i] = p;
            }
        } else {
            for (int i = lane; i < SS; i += 32) row[i] *= inv;
        }
    }

    // ---- Phase C: rep = P @ V ----
    float a0 = 0.f, a1 = 0.f;
    for (int kc = 0; kc < SS / 64; kc++) {
        __syncthreads();
        const float* vchunk = Vp + ((size_t)b * SS + kc * 64) * DD + h * DEPTH;
        for (int i = tid; i < 1024; i += 256) {
            int key = i >> 4, d4 = (i & 15) << 2;
            *(float4*)&kt[key * 64 + d4] = *(const float4*)(vchunk + (size_t)key * DD + d4);
        }
        __syncthreads();
#pragma unroll
        for (int kk = 0; kk < 64; kk++) {
            float vv = kt[kk * 64 + j];
            a0 += sc[rg * SS + kc * 64 + kk] * vv;
            a1 += sc[(rg + 4) * SS + kc * 64 + kk] * vv;
        }
    }
    concat[((size_t)b * SS + qbase + rg) * DD + h * DEPTH + j]     = a0;
    concat[((size_t)b * SS + qbase + rg + 4) * DD + h * DEPTH + j] = a1;
}

// ---------------------------------------------------------------------------
extern "C" void kernel_launch(void* const* d_in, const int* in_sizes, int n_in,
                              void* d_out, int out_size)
{
    const float* Q    = (const float*)d_in[0];
    const float* K    = (const float*)d_in[1];
    const float* V    = (const float*)d_in[2];
    const float* Mask = (const float*)d_in[3];
    const float* Wq   = (const float*)d_in[4];
    const float* bq   = (const float*)d_in[5];
    const float* Wk   = (const float*)d_in[6];
    const float* bk   = (const float*)d_in[7];
    const float* Wv   = (const float*)d_in[8];
    const float* bv   = (const float*)d_in[9];
    const float* Wo   = (const float*)d_in[10];
    const float* bo   = (const float*)d_in[11];

    float* out = (float*)d_out;
    const size_t BSD = (size_t)BB * SS * DD;                 // 8,388,608
    const size_t ASZ = (size_t)BB * HH * SS * SS;            // 268,435,456
    float* attn = nullptr;
    if ((size_t)out_size >= BSD + ASZ) attn = out + BSD;

    float *gq, *gk, *gv, *gc;
    cudaGetSymbolAddress((void**)&gq, g_q);
    cudaGetSymbolAddress((void**)&gk, g_k);
    cudaGetSymbolAddress((void**)&gv, g_v);
    cudaGetSymbolAddress((void**)&gc, g_c);

    const int M = BB * SS;   // 8192
    dim3 ggrid(DD / 64, M / 64);   // (16, 128)

    gemm_bias_kernel<<<ggrid, 256>>>(Q, Wq, bq, gq, M, DD, DD);
    gemm_bias_kernel<<<ggrid, 256>>>(K, Wk, bk, gk, M, DD, DD);
    gemm_bias_kernel<<<ggrid, 256>>>(V, Wv, bv, gv, M, DD, DD);

    cudaFuncSetAttribute(attn_kernel,
                         cudaFuncAttributeMaxDynamicSharedMemorySize,
                         ATT_SMEM_BYTES);
    dim3 agrid(SS / QBLK, HH, BB);   // (256, 16, 4)
    attn_kernel<<<agrid, 256, ATT_SMEM_BYTES>>>(gq, gk, gv, Mask, attn, gc);

    gemm_bias_kernel<<<ggrid, 256>>>(gc, Wo, bo, out, M, DD, DD);
}

// round 3
// speedup vs baseline: 2.7360x; 2.7360x over previous
#include <cuda_runtime.h>
#include <stdint.h>
#include <stddef.h>

// Problem constants
#define BB 4
#define SS 2048
#define DD 1024
#define HH 16
#define DEPTH 64

// Scratch (allocation-free: __device__ globals)
__device__ float g_q[(size_t)BB * SS * DD];
__device__ float g_k[(size_t)BB * SS * DD];
__device__ float g_v[(size_t)BB * SS * DD];
__device__ float g_c[(size_t)BB * SS * DD];

// ---------------------------------------------------------------------------
// tf32 helpers: error-compensated split (tf32x3) + m16n8k8 mma
// ---------------------------------------------------------------------------
__device__ __forceinline__ uint32_t f2tf(float x) {
    uint32_t r;
    asm("cvt.rna.tf32.f32 %0, %1;" : "=r"(r) : "f"(x));
    return r;
}
__device__ __forceinline__ void split_tf(float x, uint32_t& hi, uint32_t& lo) {
    hi = f2tf(x);
    lo = f2tf(x - __uint_as_float(hi));
}
__device__ __forceinline__ void mma8(float* d, const uint32_t* a, const uint32_t* b) {
    asm volatile(
        "mma.sync.aligned.m16n8k8.row.col.f32.tf32.tf32.f32 "
        "{%0,%1,%2,%3}, {%4,%5,%6,%7}, {%8,%9}, {%0,%1,%2,%3};\n"
        : "+f"(d[0]), "+f"(d[1]), "+f"(d[2]), "+f"(d[3])
        : "r"(a[0]), "r"(a[1]), "r"(a[2]), "r"(a[3]), "r"(b[0]), "r"(b[1]));
}
__device__ __forceinline__ void cp16(void* smem, const void* g) {
    uint32_t s = (uint32_t)__cvta_generic_to_shared(smem);
    asm volatile("cp.async.cg.shared.global [%0], [%1], 16;\n" :: "r"(s), "l"(g));
}

// ---------------------------------------------------------------------------
// GEMM (tf32x3): C[M,N] = A[M,K] @ W[K,N] + bias
// Block tile 128x128, K-slice 16, 8 warps (warp tile 64x32), cp.async 2-stage.
// ---------------------------------------------------------------------------
#define APITCH 20
#define BPITCH 136

__global__ __launch_bounds__(256, 2) void gemm_tf32x3(
    const float* __restrict__ A, const float* __restrict__ W,
    const float* __restrict__ bias, float* __restrict__ C,
    int M, int N, int K)
{
    __shared__ float As[2][128 * APITCH];
    __shared__ float Bs[2][16 * BPITCH];

    const int tid = threadIdx.x;
    const int warp = tid >> 5, lane = tid & 31;
    const int g = lane >> 2, t = lane & 3;
    const int wm = warp >> 2, wn = warp & 3;
    const int bm = blockIdx.y * 128, bn = blockIdx.x * 128;

    const int ar = tid >> 2, ac = (tid & 3) << 2;     // A loader: rows ar, ar+64
    const int bkr = tid >> 5, bc = (tid & 31) << 2;   // B loader: k rows bkr, bkr+8

    const float* Abase = A + (size_t)bm * K;
    const float* Wbase = W + bn;

    float acc[4][4][4];
#pragma unroll
    for (int mi = 0; mi < 4; mi++)
#pragma unroll
        for (int ni = 0; ni < 4; ni++)
#pragma unroll
            for (int r = 0; r < 4; r++) acc[mi][ni][r] = 0.f;

#define LOADSLICE(buf, k0) do { \
    cp16(&As[buf][ar * APITCH + ac],          Abase + (size_t)ar * K + (k0) + ac); \
    cp16(&As[buf][(ar + 64) * APITCH + ac],   Abase + (size_t)(ar + 64) * K + (k0) + ac); \
    cp16(&Bs[buf][bkr * BPITCH + bc],         Wbase + (size_t)((k0) + bkr) * N + bc); \
    cp16(&Bs[buf][(bkr + 8) * BPITCH + bc],   Wbase + (size_t)((k0) + bkr + 8) * N + bc); \
    asm volatile("cp.async.commit_group;\n"); \
} while (0)

    LOADSLICE(0, 0);
    int cur = 0;
    for (int k0 = 0; k0 < K; k0 += 16) {
        asm volatile("cp.async.wait_group 0;\n");
        __syncthreads();
        if (k0 + 16 < K) LOADSLICE(cur ^ 1, k0 + 16);
        const float* as = &As[cur][0];
        const float* bs = &Bs[cur][0];
#pragma unroll
        for (int ks = 0; ks < 16; ks += 8) {
            uint32_t bhi[4][2], blo[4][2];
#pragma unroll
            for (int ni = 0; ni < 4; ni++) {
                const int c = wn * 32 + ni * 8 + g;
                split_tf(bs[(ks + t) * BPITCH + c],     bhi[ni][0], blo[ni][0]);
                split_tf(bs[(ks + t + 4) * BPITCH + c], bhi[ni][1], blo[ni][1]);
            }
#pragma unroll
            for (int mi = 0; mi < 4; mi++) {
                const int r = wm * 64 + mi * 16;
                uint32_t ahi[4], alo[4];
                split_tf(as[(r + g) * APITCH + ks + t],         ahi[0], alo[0]);
                split_tf(as[(r + 8 + g) * APITCH + ks + t],     ahi[1], alo[1]);
                split_tf(as[(r + g) * APITCH + ks + t + 4],     ahi[2], alo[2]);
                split_tf(as[(r + 8 + g) * APITCH + ks + t + 4], ahi[3], alo[3]);
#pragma unroll
                for (int ni = 0; ni < 4; ni++) {
                    mma8(acc[mi][ni], alo, bhi[ni]);
                    mma8(acc[mi][ni], ahi, blo[ni]);
                    mma8(acc[mi][ni], ahi, bhi[ni]);
                }
            }
        }
        cur ^= 1;
    }
#undef LOADSLICE

    // Epilogue: bias + store
#pragma unroll
    for (int mi = 0; mi < 4; mi++) {
#pragma unroll
        for (int ni = 0; ni < 4; ni++) {
            const int row = bm + wm * 64 + mi * 16 + g;
            const int col = bn + wn * 32 + ni * 8 + 2 * t;
            const float b0 = bias[col], b1 = bias[col + 1];
            float2 v0 = make_float2(acc[mi][ni][0] + b0, acc[mi][ni][1] + b1);
            float2 v1 = make_float2(acc[mi][ni][2] + b0, acc[mi][ni][3] + b1);
            *(float2*)&C[(size_t)row * N + col] = v0;
            *(float2*)&C[(size_t)(row + 8) * N + col] = v1;
        }
    }
}

// ---------------------------------------------------------------------------
// Attention (tf32x3 tensor-core): block = 64 q-rows of one (b,h).
// Streams 64-key chunks: S=QK^T (mma) -> exp (no max-sub; scores bounded,
// masked entries underflow to 0) -> probs to smem+global (unnormalized)
// -> O += P@V (mma). Epilogue: rowsum reduce, normalize O, rescale attn in L2.
// ---------------------------------------------------------------------------
#define AP 76
#define ATT_SMEM_FLOATS (4 * 64 * AP + 128 + 64)
#define ATT_SMEM_BYTES  (ATT_SMEM_FLOATS * 4)

__global__ __launch_bounds__(256) void attn_tc(
    const float* __restrict__ Qp, const float* __restrict__ Kp,
    const float* __restrict__ Vp, const float* __restrict__ Mask,
    float* __restrict__ attn_out, float* __restrict__ concat)
{
    extern __shared__ float sm[];
    float* Qs = sm;               // [64][AP]
    float* Ks = Qs + 64 * AP;     // [64][AP]
    float* Vs = Ks + 64 * AP;     // [64][AP]
    float* Ps = Vs + 64 * AP;     // [64][AP] mask staging / probs
    float* rs = Ps + 64 * AP;     // [2][64]
    float* inv = rs + 128;        // [64]

    const int tid = threadIdx.x;
    const int warp = tid >> 5, lane = tid & 31;
    const int g = lane >> 2, t = lane & 3;
    const int m0 = (warp & 3) * 16;   // q-row offset of warp tile
    const int n0 = (warp >> 2) * 32;  // key/depth offset of warp tile
    const int qb = blockIdx.x * 64;
    const int h = blockIdx.y;
    const int b = blockIdx.z;

    const int lr = tid >> 2, lc = tid & 3;   // tile loaders: row lr, 4 float4s

    // Load Q tile once
    {
        const float* src = Qp + ((size_t)b * SS + qb + lr) * DD + h * DEPTH;
        float* dst = Qs + lr * AP;
#pragma unroll
        for (int i = 0; i < 4; i++)
            *(float4*)(dst + ((lc + 4 * i) << 2)) = *(const float4*)(src + ((lc + 4 * i) << 2));
    }

    float oacc[4][4];
#pragma unroll
    for (int ni = 0; ni < 4; ni++)
#pragma unroll
        for (int r = 0; r < 4; r++) oacc[ni][r] = 0.f;
    float rlo = 0.f, rhi = 0.f;

    const size_t mbase = ((size_t)b * SS + qb + lr) * SS;  // mask row for loader
    float* abase_r = attn_out ? attn_out + (((size_t)b * HH + h) * SS + qb + lr) * SS : nullptr;

    for (int kc = 0; kc < 32; kc++) {
        __syncthreads();
        // Stage K, V, Mask chunks
        {
            const float* ksrc = Kp + ((size_t)b * SS + kc * 64 + lr) * DD + h * DEPTH;
            const float* vsrc = Vp + ((size_t)b * SS + kc * 64 + lr) * DD + h * DEPTH;
            const float* msrc = Mask + mbase + kc * 64;
            float* kdst = Ks + lr * AP;
            float* vdst = Vs + lr * AP;
            float* mdst = Ps + lr * AP;
#pragma unroll
            for (int i = 0; i < 4; i++) {
                const int off = (lc + 4 * i) << 2;
                *(float4*)(kdst + off) = *(const float4*)(ksrc + off);
                *(float4*)(vdst + off) = *(const float4*)(vsrc + off);
                *(float4*)(mdst + off) = *(const float4*)(msrc + off);
            }
        }
        __syncthreads();

        // S = Q @ K^T (warp tile 16x32)
        float sacc[4][4];
#pragma unroll
        for (int ni = 0; ni < 4; ni++)
#pragma unroll
            for (int r = 0; r < 4; r++) sacc[ni][r] = 0.f;

#pragma unroll
        for (int ks = 0; ks < 64; ks += 8) {
            uint32_t ahi[4], alo[4];
            split_tf(Qs[(m0 + g) * AP + ks + t],         ahi[0], alo[0]);
            split_tf(Qs[(m0 + 8 + g) * AP + ks + t],     ahi[1], alo[1]);
            split_tf(Qs[(m0 + g) * AP + ks + t + 4],     ahi[2], alo[2]);
            split_tf(Qs[(m0 + 8 + g) * AP + ks + t + 4], ahi[3], alo[3]);
#pragma unroll
            for (int ni = 0; ni < 4; ni++) {
                const int kr = n0 + ni * 8 + g;
                uint32_t bhi[2], blo[2];
                split_tf(Ks[kr * AP + ks + t],     bhi[0], blo[0]);
                split_tf(Ks[kr * AP + ks + t + 4], bhi[1], blo[1]);
                mma8(sacc[ni], alo, bhi);
                mma8(sacc[ni], ahi, blo);
                mma8(sacc[ni], ahi, bhi);
            }
        }

        // p = exp(s*scale + mask*(-1e9)); accumulate rowsums; write p to Ps
#pragma unroll
        for (int ni = 0; ni < 4; ni++) {
            const int row0 = (m0 + g) * AP, row1 = (m0 + 8 + g) * AP;
            const int col = n0 + ni * 8 + 2 * t;
            const float m00 = Ps[row0 + col], m01 = Ps[row0 + col + 1];
            const float m10 = Ps[row1 + col], m11 = Ps[row1 + col + 1];
            const float p00 = __expf(sacc[ni][0] * 0.125f - 1e9f * m00);
            const float p01 = __expf(sacc[ni][1] * 0.125f - 1e9f * m01);
            const float p10 = __expf(sacc[ni][2] * 0.125f - 1e9f * m10);
            const float p11 = __expf(sacc[ni][3] * 0.125f - 1e9f * m11);
            rlo += p00 + p01;
            rhi += p10 + p11;
            *(float2*)(Ps + row0 + col) = make_float2(p00, p01);
            *(float2*)(Ps + row1 + col) = make_float2(p10, p11);
        }
        __syncthreads();

        // Unnormalized probs -> global
        if (abase_r) {
            float* adst = abase_r + kc * 64;
            const float* psrc = Ps + lr * AP;
#pragma unroll
            for (int i = 0; i < 4; i++) {
                const int off = (lc + 4 * i) << 2;
                *(float4*)(adst + off) = *(const float4*)(psrc + off);
            }
        }

        // O += P @ V (warp tile 16x32 over depth)
#pragma unroll
        for (int ks = 0; ks < 64; ks += 8) {
            uint32_t ahi[4], alo[4];
            split_tf(Ps[(m0 + g) * AP + ks + t],         ahi[0], alo[0]);
            split_tf(Ps[(m0 + 8 + g) * AP + ks + t],     ahi[1], alo[1]);
            split_tf(Ps[(m0 + g) * AP + ks + t + 4],     ahi[2], alo[2]);
            split_tf(Ps[(m0 + 8 + g) * AP + ks + t + 4], ahi[3], alo[3]);
#pragma unroll
            for (int ni = 0; ni < 4; ni++) {
                const int vc = n0 + ni * 8 + g;
                uint32_t bhi[2], blo[2];
                split_tf(Vs[(ks + t) * AP + vc],     bhi[0], blo[0]);
                split_tf(Vs[(ks + t + 4) * AP + vc], bhi[1], blo[1]);
                mma8(oacc[ni], alo, bhi);
                mma8(oacc[ni], ahi, blo);
                mma8(oacc[ni], ahi, bhi);
            }
        }
    }

    // Rowsum reduction: over 4 lanes (t) then across warp-n halves via smem
    rlo += __shfl_xor_sync(0xffffffffu, rlo, 1);
    rlo += __shfl_xor_sync(0xffffffffu, rlo, 2);
    rhi += __shfl_xor_sync(0xffffffffu, rhi, 1);
    rhi += __shfl_xor_sync(0xffffffffu, rhi, 2);
    if (t == 0) {
        rs[(warp >> 2) * 64 + m0 + g] = rlo;
        rs[(warp >> 2) * 64 + m0 + 8 + g] = rhi;
    }
    __syncthreads();
    if (tid < 64) inv[tid] = 1.0f / (rs[tid] + rs[64 + tid]);
    __syncthreads();

    // Normalize + write O into concat layout [B*S, D] at head offset
#pragma unroll
    for (int ni = 0; ni < 4; ni++) {
        const float i0 = inv[m0 + g], i1 = inv[m0 + 8 + g];
        const size_t row = (size_t)b * SS + qb + m0 + g;
        const int col = h * DEPTH + n0 + ni * 8 + 2 * t;
        *(float2*)&concat[row * DD + col] =
            make_float2(oacc[ni][0] * i0, oacc[ni][1] * i0);
        *(float2*)&concat[(row + 8) * DD + col] =
            make_float2(oacc[ni][2] * i1, oacc[ni][3] * i1);
    }

    // Rescale attn rows in place (reads mostly hit L2)
    if (attn_out) {
        float* abase = attn_out + (((size_t)b * HH + h) * SS + qb) * SS;
        for (int idx = tid; idx < 64 * 512; idx += 256) {
            const int row = idx >> 9;
            const int c4 = idx & 511;
            const float s = inv[row];
            float4 v = *(float4*)(abase + (size_t)row * SS + (c4 << 2));
            v.x *= s; v.y *= s; v.z *= s; v.w *= s;
            *(float4*)(abase + (size_t)row * SS + (c4 << 2)) = v;
        }
    }
}

// ---------------------------------------------------------------------------
extern "C" void kernel_launch(void* const* d_in, const int* in_sizes, int n_in,
                              void* d_out, int out_size)
{
    const float* Q    = (const float*)d_in[0];
    const float* K    = (const float*)d_in[1];
    const float* V    = (const float*)d_in[2];
    const float* Mask = (const float*)d_in[3];
    const float* Wq   = (const float*)d_in[4];
    const float* bq   = (const float*)d_in[5];
    const float* Wk   = (const float*)d_in[6];
    const float* bk   = (const float*)d_in[7];
    const float* Wv   = (const float*)d_in[8];
    const float* bv   = (const float*)d_in[9];
    const float* Wo   = (const float*)d_in[10];
    const float* bo   = (const float*)d_in[11];

    float* out = (float*)d_out;
    const size_t BSD = (size_t)BB * SS * DD;
    const size_t ASZ = (size_t)BB * HH * SS * SS;
    float* attn = nullptr;
    if ((size_t)out_size >= BSD + ASZ) attn = out + BSD;

    float *gq, *gk, *gv, *gc;
    cudaGetSymbolAddress((void**)&gq, g_q);
    cudaGetSymbolAddress((void**)&gk, g_k);
    cudaGetSymbolAddress((void**)&gv, g_v);
    cudaGetSymbolAddress((void**)&gc, g_c);

    const int M = BB * SS;   // 8192
    dim3 ggrid(DD / 128, M / 128);   // (8, 64)

    gemm_tf32x3<<<ggrid, 256>>>(Q, Wq, bq, gq, M, DD, DD);
    gemm_tf32x3<<<ggrid, 256>>>(K, Wk, bk, gk, M, DD, DD);
    gemm_tf32x3<<<ggrid, 256>>>(V, Wv, bv, gv, M, DD, DD);

    cudaFuncSetAttribute(attn_tc,
                         cudaFuncAttributeMaxDynamicSharedMemorySize,
                         ATT_SMEM_BYTES);
    dim3 agrid(SS / 64, HH, BB);   // (32, 16, 4)
    attn_tc<<<agrid, 256, ATT_SMEM_BYTES>>>(gq, gk, gv, Mask, attn, gc);

    gemm_tf32x3<<<ggrid, 256>>>(gc, Wo, bo, out, M, DD, DD);
}